// round 13
// baseline (speedup 1.0000x reference)
#include <cuda_runtime.h>
#include <cuda_bf16.h>
#include <stdint.h>
#include <math.h>

// ---------------- global scratch (no allocations allowed) ----------------
// split-K partials: [ks=16][n=256][o stride 132] (o: 0..127 = M^T, 128 = d)
__device__ __align__(16) float g_part[16 * 256 * 132];
// B fragments: [Tg=32][s=8][lane=32] uint4 {b0_hi, b1_hi, b0_lo, b1_lo}
__device__ __align__(16) uint4 g_bfr[32 * 8 * 32];
__device__ __align__(16) float g_d[256];
__device__ __align__(16) float g_c8[256];
__device__ __align__(16) float g_alpha[16];
__device__ unsigned g_cnt16[16] = {};   // per-n-group arrival counters (reset each launch)

// ---------------- helpers ----------------
__device__ __forceinline__ void hilo(float2 f, uint32_t& h, uint32_t& l) {
    __nv_bfloat16 ax = __float2bfloat16(f.x), ay = __float2bfloat16(f.y);
    __nv_bfloat162 hv; hv.x = ax; hv.y = ay;
    float rx = f.x - __bfloat162float(ax);
    float ry = f.y - __bfloat162float(ay);
    __nv_bfloat162 lv = __floats2bfloat162_rn(rx, ry);
    h = *reinterpret_cast<uint32_t*>(&hv);
    l = *reinterpret_cast<uint32_t*>(&lv);
}

__device__ __forceinline__ void mma16816(float* c, const uint32_t* a, uint32_t b0, uint32_t b1) {
    asm volatile(
        "mma.sync.aligned.m16n8k16.row.col.f32.bf16.bf16.f32 "
        "{%0,%1,%2,%3}, {%4,%5,%6,%7}, {%8,%9}, {%0,%1,%2,%3};\n"
        : "+f"(c[0]), "+f"(c[1]), "+f"(c[2]), "+f"(c[3])
        : "r"(a[0]), "r"(a[1]), "r"(a[2]), "r"(a[3]), "r"(b0), "r"(b1));
}

// ================= kernel 1: split-K partial GEMM + fused last-CTA pack =================
// (R12 version, measured — hot path untouched)
__global__ __launch_bounds__(256) void prep1(const float* __restrict__ A,     // pre_fc_w (128,512)
                                             const float* __restrict__ bias,  // pre_fc_b (512,)
                                             const float* __restrict__ vw,    // value_w (512,1024)
                                             const float* __restrict__ pw,    // p_w (16,64)
                                             const float* __restrict__ pb,    // p_b (64,)
                                             const float* __restrict__ vb) {  // value_b (1024,)
    int tid = threadIdx.x;
    int nt = blockIdx.x, ks = blockIdx.y;

    if (nt == 16) {
        if (ks != 0) return;
        float c = 0.25f * (vb[tid] + vb[tid + 256] + vb[tid + 512] + vb[tid + 768]);
        g_c8[tid] = 0.125f * c;
        __shared__ float s16[16 * 64];
        for (int i = tid; i < 16 * 64; i += 256) s16[i] = pw[i] + pb[i & 63];
        __syncthreads();
        if (tid < 16) {
            float* s = s16 + tid * 64;
            float S = 0.f;
            for (int t8 = 0; t8 < 8; t8++) {
                float bv = -1e30f; int bi = 0;
                for (int n = 0; n < 64; n++) {
                    float v = s[n];
                    if (v > bv) { bv = v; bi = n; }
                }
                S += 1.f / (1.f + expf(-bv));   // softmax([x,0])[0] = sigmoid(x)
                s[bi] = -1e30f;
            }
            g_alpha[tid] = S * (1.0f / 64.0f);
        }
        return;
    }

    __shared__ __align__(16) float sA[129 * 36];   // [o][k], LD=36
    __shared__ __align__(16) float sB[32 * 16];    // [k][n]
    int n0 = nt * 16, k0 = ks * 32;

    #pragma unroll
    for (int i = 0; i < 5; i++) {
        int fid = tid + i * 256;
        if (fid < 129 * 8) {
            int row = fid >> 3, kq = fid & 7;
            float4 v = (row < 128) ? *(const float4*)(A + (size_t)row * 512 + k0 + kq * 4)
                                   : *(const float4*)(bias + k0 + kq * 4);
            *(float4*)(sA + row * 36 + kq * 4) = v;
        }
    }
    #pragma unroll
    for (int i = 0; i < 2; i++) {
        int idx = tid + i * 256;
        int k = idx >> 4, j = idx & 15;
        const float* p = vw + (size_t)(k0 + k) * 1024 + n0 + j;
        sB[k * 16 + j] = 0.25f * (p[0] + p[256] + p[512] + p[768]);
    }
    __syncthreads();

    int tx = tid & 3, ty = tid >> 2;
    float acc0[4] = {}, acc1[4] = {}, accb[4] = {};
    #pragma unroll
    for (int k = 0; k < 32; k++) {
        float4 b4 = *(const float4*)&sB[k * 16 + tx * 4];
        float a0 = sA[ty * 36 + k];
        float a1 = sA[(ty + 64) * 36 + k];
        acc0[0] = fmaf(a0, b4.x, acc0[0]); acc0[1] = fmaf(a0, b4.y, acc0[1]);
        acc0[2] = fmaf(a0, b4.z, acc0[2]); acc0[3] = fmaf(a0, b4.w, acc0[3]);
        acc1[0] = fmaf(a1, b4.x, acc1[0]); acc1[1] = fmaf(a1, b4.y, acc1[1]);
        acc1[2] = fmaf(a1, b4.z, acc1[2]); acc1[3] = fmaf(a1, b4.w, acc1[3]);
        if (ty == 0) {
            float ab = sA[128 * 36 + k];
            accb[0] = fmaf(ab, b4.x, accb[0]); accb[1] = fmaf(ab, b4.y, accb[1]);
            accb[2] = fmaf(ab, b4.z, accb[2]); accb[3] = fmaf(ab, b4.w, accb[3]);
        }
    }
    #pragma unroll
    for (int j = 0; j < 4; j++) {
        size_t base = ((size_t)ks * 256 + n0 + tx * 4 + j) * 132;
        g_part[base + ty]      = acc0[j];
        g_part[base + ty + 64] = acc1[j];
        if (ty == 0) g_part[base + 128] = accb[j];
    }

    // ---- last-CTA-done pack for column group nt ----
    __threadfence();
    __syncthreads();
    __shared__ unsigned s_last;
    if (tid == 0) s_last = (atomicAdd(&g_cnt16[nt], 1u) == 15u) ? 1u : 0u;
    __syncthreads();
    if (!s_last) return;
    if (tid == 0) atomicExch(&g_cnt16[nt], 0u);    // reset for next launch (replay-safe)

    #pragma unroll
    for (int e = 0; e < 2; e++) {
        int p = nt * 512 + e * 256 + tid;          // == (Tg*8+s)*32+lane
        int lane = p & 31, s = (p >> 5) & 7;
        int n = (p >> 8) * 8 + (lane >> 2);
        int o0 = s * 16 + (lane & 3) * 2;
        float2 f0 = {0.f, 0.f}, f1 = {0.f, 0.f};
        #pragma unroll
        for (int kk = 0; kk < 16; kk++) {
            const float* q = &g_part[((size_t)kk * 256 + n) * 132];
            float2 u = __ldcg((const float2*)(q + o0));
            float2 v = __ldcg((const float2*)(q + o0 + 8));
            f0.x += u.x; f0.y += u.y; f1.x += v.x; f1.y += v.y;
        }
        uint4 qv; uint32_t l0, l1;
        hilo(f0, qv.x, l0); hilo(f1, qv.y, l1);
        qv.z = l0; qv.w = l1;
        g_bfr[p] = qv;
    }
    if (tid < 16) {
        int n = nt * 16 + tid;
        float d = 0.f;
        #pragma unroll
        for (int kk = 0; kk < 16; kk++)
            d += __ldcg(&g_part[((size_t)kk * 256 + n) * 132 + 128]);
        g_d[n] = d;
    }
}

// ================= kernel 2: main HMMA GEMM, 512 threads (16 warps) =================
// CTA tile 64m x 128n; grid (128, 2) = 256 CTAs, all co-resident (2/SM).
// 16 warps = 2(wm) x 8(wn): each warp 2 m-frags x 2 Tg-tiles = 96 MMAs.
// Doubles warps/SM (13.8 -> ~27.7) to cover the L2/DRAM latency chain that
// dominated the 256-thread version (occ 21.4%, issue 13.1%).
static constexpr int MO_AH  = 0;        // uint4[1024] = 16384 (A hi) ── overlaid with EPI
static constexpr int MO_AL  = 16384;    // uint4[1024] = 16384 (A lo) ──┘
static constexpr int MO_EPI = 0;        // float[64][132] = 33792 (post-mma scratch)
static constexpr int MO_DS  = 33792;    // float[128]
static constexpr int MO_C8  = 34304;    // float[128]
static constexpr int MO_ALS = 34816;    // float[64]
static constexpr int MSMEM  = 35072;

__global__ __launch_bounds__(512, 2) void main_hmma(const float* __restrict__ x,   // (8192,128)
                                                    const int* __restrict__ opt,   // (8192,)
                                                    float* __restrict__ out) {     // (8192,256)
    extern __shared__ __align__(16) char sm[];
    uint4* ah_s = (uint4*)(sm + MO_AH);
    uint4* al_s = (uint4*)(sm + MO_AL);
    float* epi  = (float*)(sm + MO_EPI);
    float* ds   = (float*)(sm + MO_DS);
    float* c8s  = (float*)(sm + MO_C8);
    float* als  = (float*)(sm + MO_ALS);

    int tid = threadIdx.x;
    int m0 = blockIdx.x * 64;
    int nt = blockIdx.y, n0 = nt * 128;

    if (tid < 128) { ds[tid] = g_d[n0 + tid]; c8s[tid] = g_c8[n0 + tid]; }
    else if (tid < 192) als[tid - 128] = g_alpha[opt[m0 + tid - 128]];

    // stage A fragments (hi/lo separate, lane-contiguous): 1024 pairs / 512 threads
    #pragma unroll
    for (int i = 0; i < 2; i++) {
        int p = tid + i * 512;
        int lane_ = p & 31, s = (p >> 5) & 7, mf = p >> 8;
        int row = m0 + mf * 16 + (lane_ >> 2);
        int k0 = s * 16 + (lane_ & 3) * 2;
        const float* xr = x + (size_t)row * 128;
        float2 xa = *(const float2*)(xr + k0);
        float2 xb = *(const float2*)(xr + 8 * 128 + k0);
        float2 xc = *(const float2*)(xr + k0 + 8);
        float2 xd = *(const float2*)(xr + 8 * 128 + k0 + 8);
        uint4 hi, lo;
        hilo(xa, hi.x, lo.x); hilo(xb, hi.y, lo.y);
        hilo(xc, hi.z, lo.z); hilo(xd, hi.w, lo.w);
        ah_s[p] = hi;
        al_s[p] = lo;
    }
    __syncthreads();

    int wid = tid >> 5, lane = tid & 31;
    int wm = wid & 1, wn = wid >> 1;           // wm: 32-row half; wn: 0..7 (16 cols = 2 Tg)
    // global Tg = nt*16 + wn*2 + t  ->  g_bfr offset ((Tg)*8 + s)*32 + lane
    const uint4* bg = g_bfr + ((nt * 16 + wn * 2) * 8) * 32 + lane;  // t stride 8*32=256, s stride 32

    float acc[2][2][4];
    #pragma unroll
    for (int a_ = 0; a_ < 2; a_++)
        #pragma unroll
        for (int b_ = 0; b_ < 2; b_++)
            #pragma unroll
            for (int c_ = 0; c_ < 4; c_++) acc[a_][b_][c_] = 0.f;

    // software-pipelined B loads (prefetch s+1 while doing s's MMAs)
    uint4 bq0 = bg[0 * 256 + 0 * 32];
    uint4 bq1 = bg[1 * 256 + 0 * 32];
    #pragma unroll
    for (int s = 0; s < 8; s++) {
        uint4 nb0, nb1;
        if (s < 7) {
            nb0 = bg[0 * 256 + (s + 1) * 32];
            nb1 = bg[1 * 256 + (s + 1) * 32];
        }
        uint4 ah[2], al[2];
        #pragma unroll
        for (int mt = 0; mt < 2; mt++) {
            int fp = ((wm * 2 + mt) * 8 + s) * 32 + lane;
            ah[mt] = ah_s[fp];
            al[mt] = al_s[fp];
        }
        #pragma unroll
        for (int mt = 0; mt < 2; mt++) {
            mma16816(acc[mt][0], (const uint32_t*)&ah[mt], bq0.x, bq0.y);
            mma16816(acc[mt][0], (const uint32_t*)&ah[mt], bq0.z, bq0.w);
            mma16816(acc[mt][0], (const uint32_t*)&al[mt], bq0.x, bq0.y);
            mma16816(acc[mt][1], (const uint32_t*)&ah[mt], bq1.x, bq1.y);
            mma16816(acc[mt][1], (const uint32_t*)&ah[mt], bq1.z, bq1.w);
            mma16816(acc[mt][1], (const uint32_t*)&al[mt], bq1.x, bq1.y);
        }
        if (s < 7) { bq0 = nb0; bq1 = nb1; }
    }

    // --- epilogue: raw accs -> smem (overwrites A frags), coalesced read-back ---
    __syncthreads();
    int g = lane >> 2, tq = lane & 3;
    #pragma unroll
    for (int mt = 0; mt < 2; mt++) {
        int rl = wm * 32 + mt * 16 + g;
        #pragma unroll
        for (int t = 0; t < 2; t++) {
            int nl = wn * 16 + t * 8 + tq * 2;
            float* c = acc[mt][t];
            *(float2*)&epi[rl * 132 + nl]       = make_float2(c[0], c[1]);
            *(float2*)&epi[(rl + 8) * 132 + nl] = make_float2(c[2], c[3]);
        }
    }
    float4 dd = *(const float4*)&ds[lane * 4];
    float4 cc = *(const float4*)&c8s[lane * 4];
    __syncthreads();

    #pragma unroll
    for (int it = 0; it < 4; it++) {
        int row = wid * 4 + it;
        float a = als[row];
        float4 v = *(const float4*)&epi[row * 132 + lane * 4];
        float4 o;
        o.x = fmaf(v.x + dd.x, a, cc.x);
        o.y = fmaf(v.y + dd.y, a, cc.y);
        o.z = fmaf(v.z + dd.z, a, cc.z);
        o.w = fmaf(v.w + dd.w, a, cc.w);
        *(float4*)&out[(size_t)(m0 + row) * 256 + n0 + lane * 4] = o;
    }
}

extern "C" void kernel_launch(void* const* d_in, const int* in_sizes, int n_in,
                              void* d_out, int out_size) {
    const float* x        = (const float*)d_in[0];   // (8192,128)
    const int*   option   = (const int*)  d_in[1];   // (8192,)
    const float* pre_fc_w = (const float*)d_in[2];   // (128,512)
    const float* pre_fc_b = (const float*)d_in[3];   // (512,)
    const float* value_w  = (const float*)d_in[4];   // (512,1024)
    const float* value_b  = (const float*)d_in[5];   // (1024,)
    const float* p_w      = (const float*)d_in[6];   // (16,64)
    const float* p_b      = (const float*)d_in[7];   // (64,)
    float* out = (float*)d_out;                      // (8192,256)

    prep1<<<dim3(17, 16), 256>>>(pre_fc_w, pre_fc_b, value_w, p_w, p_b, value_b);
    main_hmma<<<dim3(128, 2), 512, MSMEM>>>(x, option, out);
}

// round 14
// speedup vs baseline: 1.0070x; 1.0070x over previous
#include <cuda_runtime.h>
#include <cuda_bf16.h>
#include <cuda_fp16.h>
#include <stdint.h>
#include <math.h>

// ---------------- global scratch (no allocations allowed) ----------------
// split-K partials: [ks=16][n=256][o stride 132] (o: 0..127 = M^T, 128 = d)
__device__ __align__(16) float g_part[16 * 256 * 132];
// B fragments: [Tg=32][s=8][lane=32] uint4 {b0_hi, b1_hi, b0_lo, b1_lo} (fp16 pairs)
__device__ __align__(16) uint4 g_bfr[32 * 8 * 32];
__device__ __align__(16) float g_d[256];
__device__ __align__(16) float g_c8[256];
__device__ __align__(16) float g_alpha[16];
__device__ unsigned g_cnt16[16] = {};   // per-n-group arrival counters (reset each launch)

// ---------------- helpers ----------------
// fp16 hi/lo split of an fp32 pair (B side: Mh + Ml captures ~22 mantissa bits)
__device__ __forceinline__ void hilo_h(float2 f, uint32_t& h, uint32_t& l) {
    __half2 hv = __floats2half2_rn(f.x, f.y);
    float rx = f.x - __half2float(__low2half(hv));
    float ry = f.y - __half2float(__high2half(hv));
    __half2 lv = __floats2half2_rn(rx, ry);
    h = *reinterpret_cast<uint32_t*>(&hv);
    l = *reinterpret_cast<uint32_t*>(&lv);
}

__device__ __forceinline__ uint32_t h2pack(float2 f) {
    __half2 hv = __floats2half2_rn(f.x, f.y);
    return *reinterpret_cast<uint32_t*>(&hv);
}

__device__ __forceinline__ void mma16816h(float* c, const uint32_t* a, uint32_t b0, uint32_t b1) {
    asm volatile(
        "mma.sync.aligned.m16n8k16.row.col.f32.f16.f16.f32 "
        "{%0,%1,%2,%3}, {%4,%5,%6,%7}, {%8,%9}, {%0,%1,%2,%3};\n"
        : "+f"(c[0]), "+f"(c[1]), "+f"(c[2]), "+f"(c[3])
        : "r"(a[0]), "r"(a[1]), "r"(a[2]), "r"(a[3]), "r"(b0), "r"(b1));
}

// ================= kernel 1: split-K partial GEMM + fused last-CTA pack =================
// (R12 hot path untouched; only the pack conversion switched to fp16 hi/lo)
__global__ __launch_bounds__(256) void prep1(const float* __restrict__ A,     // pre_fc_w (128,512)
                                             const float* __restrict__ bias,  // pre_fc_b (512,)
                                             const float* __restrict__ vw,    // value_w (512,1024)
                                             const float* __restrict__ pw,    // p_w (16,64)
                                             const float* __restrict__ pb,    // p_b (64,)
                                             const float* __restrict__ vb) {  // value_b (1024,)
    int tid = threadIdx.x;
    int nt = blockIdx.x, ks = blockIdx.y;

    if (nt == 16) {
        if (ks != 0) return;
        float c = 0.25f * (vb[tid] + vb[tid + 256] + vb[tid + 512] + vb[tid + 768]);
        g_c8[tid] = 0.125f * c;
        __shared__ float s16[16 * 64];
        for (int i = tid; i < 16 * 64; i += 256) s16[i] = pw[i] + pb[i & 63];
        __syncthreads();
        if (tid < 16) {
            float* s = s16 + tid * 64;
            float S = 0.f;
            for (int t8 = 0; t8 < 8; t8++) {
                float bv = -1e30f; int bi = 0;
                for (int n = 0; n < 64; n++) {
                    float v = s[n];
                    if (v > bv) { bv = v; bi = n; }
                }
                S += 1.f / (1.f + expf(-bv));   // softmax([x,0])[0] = sigmoid(x)
                s[bi] = -1e30f;
            }
            g_alpha[tid] = S * (1.0f / 64.0f);
        }
        return;
    }

    __shared__ __align__(16) float sA[129 * 36];   // [o][k], LD=36
    __shared__ __align__(16) float sB[32 * 16];    // [k][n]
    int n0 = nt * 16, k0 = ks * 32;

    #pragma unroll
    for (int i = 0; i < 5; i++) {
        int fid = tid + i * 256;
        if (fid < 129 * 8) {
            int row = fid >> 3, kq = fid & 7;
            float4 v = (row < 128) ? *(const float4*)(A + (size_t)row * 512 + k0 + kq * 4)
                                   : *(const float4*)(bias + k0 + kq * 4);
            *(float4*)(sA + row * 36 + kq * 4) = v;
        }
    }
    #pragma unroll
    for (int i = 0; i < 2; i++) {
        int idx = tid + i * 256;
        int k = idx >> 4, j = idx & 15;
        const float* p = vw + (size_t)(k0 + k) * 1024 + n0 + j;
        sB[k * 16 + j] = 0.25f * (p[0] + p[256] + p[512] + p[768]);
    }
    __syncthreads();

    int tx = tid & 3, ty = tid >> 2;
    float acc0[4] = {}, acc1[4] = {}, accb[4] = {};
    #pragma unroll
    for (int k = 0; k < 32; k++) {
        float4 b4 = *(const float4*)&sB[k * 16 + tx * 4];
        float a0 = sA[ty * 36 + k];
        float a1 = sA[(ty + 64) * 36 + k];
        acc0[0] = fmaf(a0, b4.x, acc0[0]); acc0[1] = fmaf(a0, b4.y, acc0[1]);
        acc0[2] = fmaf(a0, b4.z, acc0[2]); acc0[3] = fmaf(a0, b4.w, acc0[3]);
        acc1[0] = fmaf(a1, b4.x, acc1[0]); acc1[1] = fmaf(a1, b4.y, acc1[1]);
        acc1[2] = fmaf(a1, b4.z, acc1[2]); acc1[3] = fmaf(a1, b4.w, acc1[3]);
        if (ty == 0) {
            float ab = sA[128 * 36 + k];
            accb[0] = fmaf(ab, b4.x, accb[0]); accb[1] = fmaf(ab, b4.y, accb[1]);
            accb[2] = fmaf(ab, b4.z, accb[2]); accb[3] = fmaf(ab, b4.w, accb[3]);
        }
    }
    #pragma unroll
    for (int j = 0; j < 4; j++) {
        size_t base = ((size_t)ks * 256 + n0 + tx * 4 + j) * 132;
        g_part[base + ty]      = acc0[j];
        g_part[base + ty + 64] = acc1[j];
        if (ty == 0) g_part[base + 128] = accb[j];
    }

    // ---- last-CTA-done pack for column group nt ----
    __threadfence();
    __syncthreads();
    __shared__ unsigned s_last;
    if (tid == 0) s_last = (atomicAdd(&g_cnt16[nt], 1u) == 15u) ? 1u : 0u;
    __syncthreads();
    if (!s_last) return;
    if (tid == 0) atomicExch(&g_cnt16[nt], 0u);    // reset for next launch (replay-safe)

    #pragma unroll
    for (int e = 0; e < 2; e++) {
        int p = nt * 512 + e * 256 + tid;          // == (Tg*8+s)*32+lane
        int lane = p & 31, s = (p >> 5) & 7;
        int n = (p >> 8) * 8 + (lane >> 2);
        int o0 = s * 16 + (lane & 3) * 2;
        float2 f0 = {0.f, 0.f}, f1 = {0.f, 0.f};
        #pragma unroll
        for (int kk = 0; kk < 16; kk++) {
            const float* q = &g_part[((size_t)kk * 256 + n) * 132];
            float2 u = __ldcg((const float2*)(q + o0));
            float2 v = __ldcg((const float2*)(q + o0 + 8));
            f0.x += u.x; f0.y += u.y; f1.x += v.x; f1.y += v.y;
        }
        uint4 qv; uint32_t l0, l1;
        hilo_h(f0, qv.x, l0); hilo_h(f1, qv.y, l1);
        qv.z = l0; qv.w = l1;
        g_bfr[p] = qv;
    }
    if (tid < 16) {
        int n = nt * 16 + tid;
        float d = 0.f;
        #pragma unroll
        for (int kk = 0; kk < 16; kk++)
            d += __ldcg(&g_part[((size_t)kk * 256 + n) * 132 + 128]);
        g_d[n] = d;
    }
}

// ================= kernel 2: main HMMA GEMM, fp16 2-product =================
// out ~= fp16(x) @ (Mh + Ml):  per (s, t, mt) only 2 MMAs (was 3).
// CTA tile 64m x 128n; grid (128, 2); 512 threads (16 warps = 2(wm) x 8(wn)).
static constexpr int MO_AH  = 0;        // uint4[1024] = 16384 (A hi only) ── overlaid with EPI
static constexpr int MO_EPI = 0;        // float[64][132] = 33792 (post-mma scratch)
static constexpr int MO_DS  = 33792;    // float[128]
static constexpr int MO_C8  = 34304;    // float[128]
static constexpr int MO_ALS = 34816;    // float[64]
static constexpr int MSMEM  = 35072;

__global__ __launch_bounds__(512, 2) void main_hmma(const float* __restrict__ x,   // (8192,128)
                                                    const int* __restrict__ opt,   // (8192,)
                                                    float* __restrict__ out) {     // (8192,256)
    extern __shared__ __align__(16) char sm[];
    uint4* ah_s = (uint4*)(sm + MO_AH);
    float* epi  = (float*)(sm + MO_EPI);
    float* ds   = (float*)(sm + MO_DS);
    float* c8s  = (float*)(sm + MO_C8);
    float* als  = (float*)(sm + MO_ALS);

    int tid = threadIdx.x;
    int m0 = blockIdx.x * 64;
    int nt = blockIdx.y, n0 = nt * 128;

    if (tid < 128) { ds[tid] = g_d[n0 + tid]; c8s[tid] = g_c8[n0 + tid]; }
    else if (tid < 192) als[tid - 128] = g_alpha[opt[m0 + tid - 128]];

    // stage A fragments (fp16 hi only): 1024 frags / 512 threads
    #pragma unroll
    for (int i = 0; i < 2; i++) {
        int p = tid + i * 512;
        int lane_ = p & 31, s = (p >> 5) & 7, mf = p >> 8;
        int row = m0 + mf * 16 + (lane_ >> 2);
        int k0 = s * 16 + (lane_ & 3) * 2;
        const float* xr = x + (size_t)row * 128;
        uint4 hi;
        hi.x = h2pack(*(const float2*)(xr + k0));
        hi.y = h2pack(*(const float2*)(xr + 8 * 128 + k0));
        hi.z = h2pack(*(const float2*)(xr + k0 + 8));
        hi.w = h2pack(*(const float2*)(xr + 8 * 128 + k0 + 8));
        ah_s[p] = hi;
    }
    __syncthreads();

    int wid = tid >> 5, lane = tid & 31;
    int wm = wid & 1, wn = wid >> 1;           // wm: 32-row half; wn: 0..7 (16 cols = 2 Tg)
    const uint4* bg = g_bfr + ((nt * 16 + wn * 2) * 8) * 32 + lane;  // t stride 256, s stride 32

    float acc[2][2][4];
    #pragma unroll
    for (int a_ = 0; a_ < 2; a_++)
        #pragma unroll
        for (int b_ = 0; b_ < 2; b_++)
            #pragma unroll
            for (int c_ = 0; c_ < 4; c_++) acc[a_][b_][c_] = 0.f;

    // software-pipelined B loads (prefetch s+1 while doing s's MMAs)
    uint4 bq0 = bg[0 * 256 + 0 * 32];
    uint4 bq1 = bg[1 * 256 + 0 * 32];
    #pragma unroll
    for (int s = 0; s < 8; s++) {
        uint4 nb0, nb1;
        if (s < 7) {
            nb0 = bg[0 * 256 + (s + 1) * 32];
            nb1 = bg[1 * 256 + (s + 1) * 32];
        }
        uint4 ah[2];
        #pragma unroll
        for (int mt = 0; mt < 2; mt++)
            ah[mt] = ah_s[((wm * 2 + mt) * 8 + s) * 32 + lane];
        #pragma unroll
        for (int mt = 0; mt < 2; mt++) {
            mma16816h(acc[mt][0], (const uint32_t*)&ah[mt], bq0.x, bq0.y);  // x_h * M_h
            mma16816h(acc[mt][0], (const uint32_t*)&ah[mt], bq0.z, bq0.w);  // x_h * M_l
            mma16816h(acc[mt][1], (const uint32_t*)&ah[mt], bq1.x, bq1.y);
            mma16816h(acc[mt][1], (const uint32_t*)&ah[mt], bq1.z, bq1.w);
        }
        if (s < 7) { bq0 = nb0; bq1 = nb1; }
    }

    // --- epilogue: raw accs -> smem (overwrites A frags), coalesced read-back ---
    __syncthreads();
    int g = lane >> 2, tq = lane & 3;
    #pragma unroll
    for (int mt = 0; mt < 2; mt++) {
        int rl = wm * 32 + mt * 16 + g;
        #pragma unroll
        for (int t = 0; t < 2; t++) {
            int nl = wn * 16 + t * 8 + tq * 2;
            float* c = acc[mt][t];
            *(float2*)&epi[rl * 132 + nl]       = make_float2(c[0], c[1]);
            *(float2*)&epi[(rl + 8) * 132 + nl] = make_float2(c[2], c[3]);
        }
    }
    float4 dd = *(const float4*)&ds[lane * 4];
    float4 cc = *(const float4*)&c8s[lane * 4];
    __syncthreads();

    #pragma unroll
    for (int it = 0; it < 4; it++) {
        int row = wid * 4 + it;
        float a = als[row];
        float4 v = *(const float4*)&epi[row * 132 + lane * 4];
        float4 o;
        o.x = fmaf(v.x + dd.x, a, cc.x);
        o.y = fmaf(v.y + dd.y, a, cc.y);
        o.z = fmaf(v.z + dd.z, a, cc.z);
        o.w = fmaf(v.w + dd.w, a, cc.w);
        *(float4*)&out[(size_t)(m0 + row) * 256 + n0 + lane * 4] = o;
    }
}

extern "C" void kernel_launch(void* const* d_in, const int* in_sizes, int n_in,
                              void* d_out, int out_size) {
    const float* x        = (const float*)d_in[0];   // (8192,128)
    const int*   option   = (const int*)  d_in[1];   // (8192,)
    const float* pre_fc_w = (const float*)d_in[2];   // (128,512)
    const float* pre_fc_b = (const float*)d_in[3];   // (512,)
    const float* value_w  = (const float*)d_in[4];   // (512,1024)
    const float* value_b  = (const float*)d_in[5];   // (1024,)
    const float* p_w      = (const float*)d_in[6];   // (16,64)
    const float* p_b      = (const float*)d_in[7];   // (64,)
    float* out = (float*)d_out;                      // (8192,256)

    prep1<<<dim3(17, 16), 256>>>(pre_fc_w, pre_fc_b, value_w, p_w, p_b, value_b);
    main_hmma<<<dim3(128, 2), 512, MSMEM>>>(x, option, out);
}

// round 15
// speedup vs baseline: 1.0845x; 1.0769x over previous
#include <cuda_runtime.h>
#include <cuda_fp16.h>
#include <stdint.h>
#include <math.h>

// ---------------- global scratch (no allocations allowed) ----------------
// split-K partials: [ks=16][n=256][o stride 132] (o: 0..127 = M^T, 128 = d)
__device__ __align__(16) float g_part[16 * 256 * 132];
// B fragments: [Tg=32][s=8][lane=32] uint4 {b0_hi, b1_hi, b0_lo, b1_lo} (fp16 pairs)
__device__ __align__(16) uint4 g_bfr[32 * 8 * 32];
__device__ __align__(16) float g_d[256];
__device__ __align__(16) float g_c8[256];
__device__ __align__(16) float g_alpha[16];
__device__ unsigned g_cnt16[16] = {};   // per-n-group arrival counters (packer resets)
__device__ unsigned g_done = 0;         // release counter: 16 packers + 1 LUT = 17
__device__ unsigned g_main_done = 0;    // main completion counter (last resets both)

// ---------------- helpers ----------------
__device__ __forceinline__ void hilo_h(float2 f, uint32_t& h, uint32_t& l) {
    __half2 hv = __floats2half2_rn(f.x, f.y);
    float rx = f.x - __half2float(__low2half(hv));
    float ry = f.y - __half2float(__high2half(hv));
    __half2 lv = __floats2half2_rn(rx, ry);
    h = *reinterpret_cast<uint32_t*>(&hv);
    l = *reinterpret_cast<uint32_t*>(&lv);
}

__device__ __forceinline__ uint32_t h2pack(float2 f) {
    __half2 hv = __floats2half2_rn(f.x, f.y);
    return *reinterpret_cast<uint32_t*>(&hv);
}

__device__ __forceinline__ void mma16816h(float* c, const uint32_t* a, uint32_t b0, uint32_t b1) {
    asm volatile(
        "mma.sync.aligned.m16n8k16.row.col.f32.f16.f16.f32 "
        "{%0,%1,%2,%3}, {%4,%5,%6,%7}, {%8,%9}, {%0,%1,%2,%3};\n"
        : "+f"(c[0]), "+f"(c[1]), "+f"(c[2]), "+f"(c[3])
        : "r"(a[0]), "r"(a[1]), "r"(a[2]), "r"(a[3]), "r"(b0), "r"(b1));
}

// SMEM offsets (dynamic, 35072 B — under the 48KB default, no attr needed).
// Prep roles overlay the front of the same region.
static constexpr int MO_AH  = 0;        // uint4[1024] = 16384 (A hi) ── overlaid with EPI
static constexpr int MO_EPI = 0;        // float[64][132] = 33792
static constexpr int MO_DS  = 33792;    // float[128]
static constexpr int MO_C8  = 34304;    // float[128]
static constexpr int MO_ALS = 34816;    // float[64]
static constexpr int MSMEM  = 35072;

// ================= ONE fused kernel =================
// grid 513 x 512 threads, 2 CTAs/SM (regs<=64 forced) -> capacity 296 co-resident.
// bids 0..255: prep compute (nt = bid&15, ks = bid>>4) + last-arriver pack.
// bid 256: alpha LUT + c8.  bids 257..512: main HMMA (waits on g_done==17).
// Deadlock-free: 256 main CTAs < 296 capacity, so prep always has slots.
__global__ __launch_bounds__(512, 2) void fused(
    const float* __restrict__ x,        // (8192,128)
    const int*   __restrict__ opt,      // (8192,)
    const float* __restrict__ A,        // pre_fc_w (128,512)
    const float* __restrict__ bias,     // pre_fc_b (512,)
    const float* __restrict__ vw,       // value_w (512,1024)
    const float* __restrict__ vb,       // value_b (1024,)
    const float* __restrict__ pw,       // p_w (16,64)
    const float* __restrict__ pb,       // p_b (64,)
    float* __restrict__ out)            // (8192,256)
{
    extern __shared__ __align__(16) char sm[];
    int tid = threadIdx.x;
    int bid = blockIdx.x;

    // ===================== role: prep compute =====================
    if (bid < 256) {
        float* sA = (float*)sm;                 // [129][36] = 18576 B
        float* sB = (float*)(sm + 18576);       // [32][16]  =  2048 B
        int nt = bid & 15, ks = bid >> 4;
        int n0 = nt * 16, k0 = ks * 32;

        // stage A (129 x 32) via float4 (1032 vec loads / 512 threads)
        #pragma unroll
        for (int i = 0; i < 3; i++) {
            int fid = tid + i * 512;
            if (fid < 129 * 8) {
                int row = fid >> 3, kq = fid & 7;
                float4 v = (row < 128) ? *(const float4*)(A + (size_t)row * 512 + k0 + kq * 4)
                                       : *(const float4*)(bias + k0 + kq * 4);
                *(float4*)(sA + row * 36 + kq * 4) = v;
            }
        }
        // stage foldW (32 k x 16 n): one cell per thread
        {
            int k = tid >> 4, j = tid & 15;
            const float* p = vw + (size_t)(k0 + k) * 1024 + n0 + j;
            sB[k * 16 + j] = 0.25f * (p[0] + p[256] + p[512] + p[768]);
        }
        __syncthreads();

        // one o-row per thread: tx = n quad, ty = row 0..127; tid<4 also bias row
        int tx = tid & 3, ty = tid >> 2;
        float acc[4] = {}, accb[4] = {};
        #pragma unroll
        for (int k = 0; k < 32; k++) {
            float4 b4 = *(const float4*)&sB[k * 16 + tx * 4];
            float a = sA[ty * 36 + k];
            acc[0] = fmaf(a, b4.x, acc[0]); acc[1] = fmaf(a, b4.y, acc[1]);
            acc[2] = fmaf(a, b4.z, acc[2]); acc[3] = fmaf(a, b4.w, acc[3]);
            if (tid < 4) {
                float ab = sA[128 * 36 + k];
                accb[0] = fmaf(ab, b4.x, accb[0]); accb[1] = fmaf(ab, b4.y, accb[1]);
                accb[2] = fmaf(ab, b4.z, accb[2]); accb[3] = fmaf(ab, b4.w, accb[3]);
            }
        }
        #pragma unroll
        for (int j = 0; j < 4; j++) {
            size_t base = ((size_t)ks * 256 + n0 + tx * 4 + j) * 132;
            g_part[base + ty] = acc[j];
            if (tid < 4) g_part[base + 128] = accb[j];
        }

        // ---- last-CTA-done pack for column group nt ----
        __threadfence();
        __syncthreads();
        __shared__ unsigned s_last;
        if (tid == 0) s_last = (atomicAdd(&g_cnt16[nt], 1u) == 15u) ? 1u : 0u;
        __syncthreads();
        if (!s_last) return;
        if (tid == 0) atomicExch(&g_cnt16[nt], 0u);    // reset (replay-safe)

        // pack 512 fragments (one per thread): p = nt*512 + tid == (Tg*8+s)*32+lane
        {
            int p = nt * 512 + tid;
            int lane = p & 31, s = (p >> 5) & 7;
            int n = (p >> 8) * 8 + (lane >> 2);
            int o0 = s * 16 + (lane & 3) * 2;
            float2 f0 = {0.f, 0.f}, f1 = {0.f, 0.f};
            #pragma unroll
            for (int kk = 0; kk < 16; kk++) {
                const float* q = &g_part[((size_t)kk * 256 + n) * 132];
                float2 u = __ldcg((const float2*)(q + o0));
                float2 v = __ldcg((const float2*)(q + o0 + 8));
                f0.x += u.x; f0.y += u.y; f1.x += v.x; f1.y += v.y;
            }
            uint4 qv; uint32_t l0, l1;
            hilo_h(f0, qv.x, l0); hilo_h(f1, qv.y, l1);
            qv.z = l0; qv.w = l1;
            g_bfr[p] = qv;
        }
        if (tid < 16) {
            int n = nt * 16 + tid;
            float d = 0.f;
            #pragma unroll
            for (int kk = 0; kk < 16; kk++)
                d += __ldcg(&g_part[((size_t)kk * 256 + n) * 132 + 128]);
            g_d[n] = d;
        }
        // signal release
        __threadfence();
        __syncthreads();
        if (tid == 0) atomicAdd(&g_done, 1u);
        return;
    }

    // ===================== role: alpha LUT + c8 =====================
    if (bid == 256) {
        float* s16 = (float*)sm;   // [16][64]
        if (tid < 256) {
            float c = 0.25f * (vb[tid] + vb[tid + 256] + vb[tid + 512] + vb[tid + 768]);
            g_c8[tid] = 0.125f * c;
        }
        for (int i = tid; i < 16 * 64; i += 512) s16[i] = pw[i] + pb[i & 63];
        __syncthreads();
        if (tid < 16) {
            float* s = s16 + tid * 64;
            float S = 0.f;
            for (int t8 = 0; t8 < 8; t8++) {
                float bv = -1e30f; int bi = 0;
                for (int n = 0; n < 64; n++) {
                    float v = s[n];
                    if (v > bv) { bv = v; bi = n; }
                }
                S += 1.f / (1.f + expf(-bv));   // softmax([x,0])[0] = sigmoid(x)
                s[bi] = -1e30f;
            }
            g_alpha[tid] = S * (1.0f / 64.0f);
        }
        __threadfence();
        __syncthreads();
        if (tid == 0) atomicAdd(&g_done, 1u);
        return;
    }

    // ===================== role: main HMMA =====================
    uint4* ah_s = (uint4*)(sm + MO_AH);
    float* epi  = (float*)(sm + MO_EPI);
    float* ds   = (float*)(sm + MO_DS);
    float* c8s  = (float*)(sm + MO_C8);
    float* als  = (float*)(sm + MO_ALS);

    int mid = bid - 257;                  // 0..255
    int m0 = (mid & 127) * 64;
    int half = mid >> 7, n0 = half * 128;

    // stage A fragments (fp16 hi only) — independent of prep, overlaps it
    #pragma unroll
    for (int i = 0; i < 2; i++) {
        int p = tid + i * 512;
        int lane_ = p & 31, s = (p >> 5) & 7, mf = p >> 8;
        int row = m0 + mf * 16 + (lane_ >> 2);
        int k0 = s * 16 + (lane_ & 3) * 2;
        const float* xr = x + (size_t)row * 128;
        uint4 hi;
        hi.x = h2pack(*(const float2*)(xr + k0));
        hi.y = h2pack(*(const float2*)(xr + 8 * 128 + k0));
        hi.z = h2pack(*(const float2*)(xr + k0 + 8));
        hi.w = h2pack(*(const float2*)(xr + 8 * 128 + k0 + 8));
        ah_s[p] = hi;
    }
    __syncthreads();

    // wait for prep release (g_done == 17); L2 reads, nanosleep backoff
    if (tid == 0) {
        for (;;) {
            unsigned v;
            asm volatile("ld.global.cg.u32 %0, [%1];" : "=r"(v) : "l"(&g_done));
            if (v >= 17u) break;
            __nanosleep(128);
        }
    }
    __syncthreads();
    __threadfence();

    // stage epilogue constants (L2 reads — L1 not coherent intra-launch)
    if (tid < 128) { ds[tid] = __ldcg(&g_d[n0 + tid]); c8s[tid] = __ldcg(&g_c8[n0 + tid]); }
    else if (tid < 192) als[tid - 128] = __ldcg(&g_alpha[opt[m0 + tid - 128]]);
    __syncthreads();

    int wid = tid >> 5, lane = tid & 31;
    int wm = wid & 1, wn = wid >> 1;      // 2(wm) x 8(wn)
    const uint4* bg = g_bfr + ((half * 16 + wn * 2) * 8) * 32 + lane;  // t stride 256, s stride 32

    float acc[2][2][4];
    #pragma unroll
    for (int a_ = 0; a_ < 2; a_++)
        #pragma unroll
        for (int b_ = 0; b_ < 2; b_++)
            #pragma unroll
            for (int c_ = 0; c_ < 4; c_++) acc[a_][b_][c_] = 0.f;

    uint4 bq0 = __ldcg(bg + 0 * 256);
    uint4 bq1 = __ldcg(bg + 1 * 256);
    #pragma unroll
    for (int s = 0; s < 8; s++) {
        uint4 nb0, nb1;
        if (s < 7) {
            nb0 = __ldcg(bg + 0 * 256 + (s + 1) * 32);
            nb1 = __ldcg(bg + 1 * 256 + (s + 1) * 32);
        }
        uint4 ah[2];
        #pragma unroll
        for (int mt = 0; mt < 2; mt++)
            ah[mt] = ah_s[((wm * 2 + mt) * 8 + s) * 32 + lane];
        #pragma unroll
        for (int mt = 0; mt < 2; mt++) {
            mma16816h(acc[mt][0], (const uint32_t*)&ah[mt], bq0.x, bq0.y);  // x_h * M_h
            mma16816h(acc[mt][0], (const uint32_t*)&ah[mt], bq0.z, bq0.w);  // x_h * M_l
            mma16816h(acc[mt][1], (const uint32_t*)&ah[mt], bq1.x, bq1.y);
            mma16816h(acc[mt][1], (const uint32_t*)&ah[mt], bq1.z, bq1.w);
        }
        if (s < 7) { bq0 = nb0; bq1 = nb1; }
    }

    // epilogue: raw accs -> smem (overwrites A frags), coalesced read-back
    __syncthreads();
    int g = lane >> 2, tq = lane & 3;
    #pragma unroll
    for (int mt = 0; mt < 2; mt++) {
        int rl = wm * 32 + mt * 16 + g;
        #pragma unroll
        for (int t = 0; t < 2; t++) {
            int nl = wn * 16 + t * 8 + tq * 2;
            float* c = acc[mt][t];
            *(float2*)&epi[rl * 132 + nl]       = make_float2(c[0], c[1]);
            *(float2*)&epi[(rl + 8) * 132 + nl] = make_float2(c[2], c[3]);
        }
    }
    float4 dd = *(const float4*)&ds[lane * 4];
    float4 cc = *(const float4*)&c8s[lane * 4];
    __syncthreads();

    #pragma unroll
    for (int it = 0; it < 4; it++) {
        int row = wid * 4 + it;
        float a = als[row];
        float4 v = *(const float4*)&epi[row * 132 + lane * 4];
        float4 o;
        o.x = fmaf(v.x + dd.x, a, cc.x);
        o.y = fmaf(v.y + dd.y, a, cc.y);
        o.z = fmaf(v.z + dd.z, a, cc.z);
        o.w = fmaf(v.w + dd.w, a, cc.w);
        *(float4*)&out[(size_t)(m0 + row) * 256 + n0 + lane * 4] = o;
    }

    // replay-safe counter reset by the last main CTA
    if (tid == 0) {
        __threadfence();
        unsigned t = atomicAdd(&g_main_done, 1u);
        if (t == 255u) {
            atomicExch(&g_main_done, 0u);
            atomicExch(&g_done, 0u);
        }
    }
}

extern "C" void kernel_launch(void* const* d_in, const int* in_sizes, int n_in,
                              void* d_out, int out_size) {
    const float* x        = (const float*)d_in[0];   // (8192,128)
    const int*   option   = (const int*)  d_in[1];   // (8192,)
    const float* pre_fc_w = (const float*)d_in[2];   // (128,512)
    const float* pre_fc_b = (const float*)d_in[3];   // (512,)
    const float* value_w  = (const float*)d_in[4];   // (512,1024)
    const float* value_b  = (const float*)d_in[5];   // (1024,)
    const float* p_w      = (const float*)d_in[6];   // (16,64)
    const float* p_b      = (const float*)d_in[7];   // (64,)
    float* out = (float*)d_out;                      // (8192,256)

    fused<<<513, 512, MSMEM>>>(x, option, pre_fc_w, pre_fc_b,
                               value_w, value_b, p_w, p_b, out);
}